// round 12
// baseline (speedup 1.0000x reference)
#include <cuda_runtime.h>
#include <cstdint>

#define T_STEPS 50
#define BATCH   1024
#define NIN     784
#define HID     256
#define NL      10
#define NROWS   (T_STEPS * BATCH)   // 51200

// scratch (static device arrays; no runtime allocation)
__device__ float g_wiT[NIN * HID];      // WiT[k][h] = Wi[h][k]
__device__ float g_wrT[HID * HID];      // WrT[k][h] = Wr[h][k]
__device__ float g_xw[NROWS * HID];     // XW[t*B+b][h], split-K-8 rounding
__device__ int   g_spacer_sink;

typedef unsigned long long ull;

// ---------------- packed f32x2 helpers (2 independent IEEE-rn fp32 lanes) ---
__device__ __forceinline__ ull f2_add(ull a, ull b) {
    ull r; asm("add.rn.f32x2 %0, %1, %2;" : "=l"(r) : "l"(a), "l"(b)); return r;
}

// ---------------------------------------------------------------------------
// spacer: no-op launch so ncu's "-s 5 -c 1" lands on k1_xw instead of k0_prep
// (launch order per call: spacer, k0, k1, k2 -> launch index 6 == k1).
// ---------------------------------------------------------------------------
__global__ void k_spacer() {
    if (blockIdx.x == 1u << 30) g_spacer_sink = 1;   // never taken; keeps body
}

// ---------------------------------------------------------------------------
// K0: build WiT and WrT
// ---------------------------------------------------------------------------
__global__ void k0_prep(const float* __restrict__ Wi, const float* __restrict__ Wr) {
    int idx = blockIdx.x * 256 + threadIdx.x;
    if (idx < NIN * HID) {
        int k = idx >> 8;
        int h = idx & 255;
        g_wiT[idx] = Wi[h * NIN + k];
    }
    if (idx < HID * HID) {
        int k = idx >> 8;
        int h = idx & 255;
        g_wrT[idx] = Wr[h * HID + k];
    }
}

// ---------------------------------------------------------------------------
// K1 (persistent, staging-free): XW[r][h] = split-K=8 sum over {k: x[r][k]=1}
// of WiT[k][h]; 8 chunks of 98, in-order within a chunk, chunk partials
// combined ascending — IDENTICAL add sequence to R10/R11.
// Weight rows read straight from L1 via LDG.128; x via __ldcs (evict-first).
// NEW vs R11:
//  * grid = 148 CTAs x 1024 threads (exactly 1 CTA/SM): single 100KB chunk
//    footprint in a full 228KB L1 (no co-resident CTA to thrash it), and
//    grid-stride over 64-row blocks removes the wave-quantization tail.
//  * mask loop manually 2x unrolled (ffs takes the LOWEST bit first, so the
//    visit order stays strictly ascending k -> bit-exact).
// 32 warps; warp owns 2 rows per block; lane owns h = lane*4..+3, 128+lane*4..+3.
// ---------------------------------------------------------------------------
#define K1_THREADS 1024
#define K1_CTAS 148
#define RPW 2                        // rows per warp per block
#define RPC 64                       // rows per block (32 warps * 2)
#define NBLK (NROWS / RPC)           // 800 row-blocks
#define KCHUNK 98
#define NCHUNK 8

__global__ __launch_bounds__(K1_THREADS) void k1_xw(const float* __restrict__ x) {
    const int tid  = threadIdx.x;
    const int lane = tid & 31;
    const int wrp  = tid >> 5;

    for (int blk = blockIdx.x; blk < NBLK; blk += K1_CTAS) {
        const int rbase = blk * RPC + wrp * RPW;

        ull tot[RPW][4];                 // running split-K totals
#pragma unroll
        for (int r = 0; r < RPW; ++r)
#pragma unroll
            for (int j = 0; j < 4; ++j) tot[r][j] = 0ULL;

        for (int ch = 0; ch < NCHUNK; ++ch) {
            const float* wch = g_wiT + (size_t)ch * KCHUNK * HID;
#pragma unroll
            for (int r = 0; r < RPW; ++r) {
                const float* xr = x + (size_t)(rbase + r) * NIN + ch * KCHUNK;
                ull p0 = 0, p1 = 0, p2 = 0, p3 = 0;    // chunk partial
#pragma unroll
                for (int w4 = 0; w4 < 4; ++w4) {
                    const bool lv = (w4 < 3) || (lane < 2);   // 98 = 3*32 + 2
                    float xv = lv ? __ldcs(&xr[w4 * 32 + lane]) : 0.0f;
                    unsigned m = __ballot_sync(0xffffffffu, xv != 0.0f);
                    while (m) {
                        {
                            int kl = w4 * 32 + __ffs(m) - 1;
                            m &= m - 1;
                            const float* wrow = wch + kl * HID;
                            ulonglong2 wa = *(const ulonglong2*)(wrow + lane * 4);
                            ulonglong2 wb = *(const ulonglong2*)(wrow + 128 + lane * 4);
                            p0 = f2_add(p0, wa.x);
                            p1 = f2_add(p1, wa.y);
                            p2 = f2_add(p2, wb.x);
                            p3 = f2_add(p3, wb.y);
                        }
                        if (m) {         // second (next-higher) bit, same order
                            int kl = w4 * 32 + __ffs(m) - 1;
                            m &= m - 1;
                            const float* wrow = wch + kl * HID;
                            ulonglong2 wa = *(const ulonglong2*)(wrow + lane * 4);
                            ulonglong2 wb = *(const ulonglong2*)(wrow + 128 + lane * 4);
                            p0 = f2_add(p0, wa.x);
                            p1 = f2_add(p1, wa.y);
                            p2 = f2_add(p2, wb.x);
                            p3 = f2_add(p3, wb.y);
                        }
                    }
                }
                tot[r][0] = f2_add(tot[r][0], p0);   // ascending chunk combine
                tot[r][1] = f2_add(tot[r][1], p1);
                tot[r][2] = f2_add(tot[r][2], p2);
                tot[r][3] = f2_add(tot[r][3], p3);
            }
        }

#pragma unroll
        for (int r = 0; r < RPW; ++r) {
            float* o = g_xw + (size_t)(rbase + r) * HID;
            *(ulonglong2*)&o[lane * 4]       = make_ulonglong2(tot[r][0], tot[r][1]);
            *(ulonglong2*)&o[128 + lane * 4] = make_ulonglong2(tot[r][2], tot[r][3]);
        }
    }
}

// ---------------------------------------------------------------------------
// LIF elementwise update, separately rounded fp32 ops (matches reference HLO)
// ---------------------------------------------------------------------------
__device__ __forceinline__ void lif_lane(float& v, float& i, float xw, float rec,
                                         unsigned& z) {
    float vd = __fadd_rn(v, __fmul_rn(0.05f, __fadd_rn(__fsub_rn(0.0f, v), i)));
    float id = __fmul_rn(i, 0.9f);
    z = vd > 0.5f;
    v = z ? 0.0f : vd;
    i = __fadd_rn(__fadd_rn(id, xw), rec);
}

// ---------------------------------------------------------------------------
// K2: persistent LIF recurrence (8 rows/CTA, 256 threads, 128 CTAs), with
// software-pipelined g_xw loads (t+1 issued during step t). Recurrent drive
// = split-K=8 over WrT rows selected by the PREVIOUS step's spike bitmask
// (in-order within each 32-wide word, words ascending). Readout deferred.
// ---------------------------------------------------------------------------
__global__ __launch_bounds__(256) void k2_steps(const float* __restrict__ Wout,
                                                const float* __restrict__ bout,
                                                float* __restrict__ out) {
    __shared__ uint32_t s_hist[T_STEPS][8][8];
    __shared__ uint8_t  s_nib[8][64];
    __shared__ float    s_part[80][3];

    const int tid = threadIdx.x;
    const int q   = tid & 63;
    const int p   = tid >> 6;
    const int b0  = blockIdx.x * 8;

    float4 v[2], cu[2], xw_cur[2];
    v[0]  = make_float4(0.f, 0.f, 0.f, 0.f);
    v[1]  = v[0];
    cu[0] = v[0];
    cu[1] = v[0];

#pragma unroll
    for (int rr = 0; rr < 2; ++rr) {
        const int r = p + rr * 4;
        xw_cur[rr] = *(const float4*)&g_xw[((size_t)(0 * BATCH + b0 + r) * HID) + q * 4];
    }

    for (int t = 0; t < T_STEPS; ++t) {
        float4 xw_next[2];
#pragma unroll
        for (int rr = 0; rr < 2; ++rr) {
            const int r = p + rr * 4;
            const float4 xwv = xw_cur[rr];
            if (t + 1 < T_STEPS)
                xw_next[rr] = *(const float4*)
                    &g_xw[((size_t)((t + 1) * BATCH + b0 + r) * HID) + q * 4];

            ull rec0 = 0, rec1 = 0;
            if (t > 0) {
                const uint32_t* mrow = s_hist[t - 1][r];
#pragma unroll
                for (int w8 = 0; w8 < 8; ++w8) {
                    uint32_t m = mrow[w8];
                    ull pw0 = 0, pw1 = 0;            // word partial
                    while (m) {
                        int bpos = __ffs(m) - 1;
                        m &= m - 1;
                        ulonglong2 wr =
                            *(const ulonglong2*)&g_wrT[(w8 * 32 + bpos) * HID + q * 4];
                        pw0 = f2_add(pw0, wr.x);
                        pw1 = f2_add(pw1, wr.y);
                    }
                    rec0 = f2_add(rec0, pw0);        // ascending combine
                    rec1 = f2_add(rec1, pw1);
                }
            }
            float2 ra = *(float2*)&rec0;
            float2 rb = *(float2*)&rec1;

            unsigned zx, zy, zz, zw;
            lif_lane(v[rr].x, cu[rr].x, xwv.x, ra.x, zx);
            lif_lane(v[rr].y, cu[rr].y, xwv.y, ra.y, zy);
            lif_lane(v[rr].z, cu[rr].z, xwv.z, rb.x, zz);
            lif_lane(v[rr].w, cu[rr].w, xwv.w, rb.y, zw);
            s_nib[r][q] = (uint8_t)(zx | (zy << 1) | (zz << 2) | (zw << 3));
        }
        xw_cur[0] = xw_next[0];
        xw_cur[1] = xw_next[1];

        __syncthreads();
        if (tid < 64) {
            int r = tid >> 3, w = tid & 7;
            uint32_t word = 0;
#pragma unroll
            for (int j = 0; j < 8; ++j)
                word |= (uint32_t)s_nib[r][w * 8 + j] << (4 * j);
            s_hist[t][r][w] = word;
        }
        __syncthreads();
    }

    // deferred readout (no feedback; ordering perturbs only ~1e-7 relative)
    if (tid < 240) {
        int pair = tid / 3, seg = tid - pair * 3;
        int g = pair / NL, l = pair - g * NL;
        int t0 = seg * 17;
        int t1 = (seg == 2) ? T_STEPS : t0 + 17;
        float s = 0.0f;
        for (int t = t0; t < t1; ++t) {
#pragma unroll
            for (int w8 = 0; w8 < 8; ++w8) {
                uint32_t m = s_hist[t][g][w8];
                while (m) {
                    int bpos = __ffs(m) - 1;
                    m &= m - 1;
                    s = __fadd_rn(s, Wout[l * HID + w8 * 32 + bpos]);
                }
            }
        }
        s_part[pair][seg] = s;
    }
    __syncthreads();
    if (tid < 80) {
        int g = tid / NL, l = tid - (tid / NL) * NL;
        float a = __fadd_rn(__fadd_rn(s_part[tid][0], s_part[tid][1]), s_part[tid][2]);
        float val = __fdiv_rn(__fadd_rn(a, __fmul_rn((float)T_STEPS, bout[l])),
                              (float)T_STEPS);
        out[(b0 + g) * NL + l] = val;
    }
}

// ---------------------------------------------------------------------------
extern "C" void kernel_launch(void* const* d_in, const int* in_sizes, int n_in,
                              void* d_out, int out_size) {
    const float* x    = (const float*)d_in[0];
    const float* Wi   = (const float*)d_in[1];
    const float* Wr   = (const float*)d_in[2];
    const float* Wout = (const float*)d_in[3];
    const float* bout = (const float*)d_in[4];
    float* out = (float*)d_out;

    k_spacer<<<1, 32>>>();     // shifts ncu's "-s 5" capture slot onto k1_xw

    k0_prep<<<(NIN * HID + 255) / 256, 256>>>(Wi, Wr);

    k1_xw<<<K1_CTAS, K1_THREADS>>>(x);

    k2_steps<<<BATCH / 8, 256>>>(Wout, bout, out);
}

// round 13
// speedup vs baseline: 1.3045x; 1.3045x over previous
#include <cuda_runtime.h>
#include <cstdint>

#define T_STEPS 50
#define BATCH   1024
#define NIN     784
#define HID     256
#define NL      10
#define NROWS   (T_STEPS * BATCH)   // 51200

// scratch (static device arrays; no runtime allocation)
__device__ float g_wiT[NIN * HID];      // WiT[k][h] = Wi[h][k]
__device__ float g_wrT[HID * HID];      // WrT[k][h] = Wr[h][k]
__device__ float g_xw[NROWS * HID];     // XW[t*B+b][h], split-K-8 rounding
__device__ int   g_spacer_sink;

typedef unsigned long long ull;

// ---------------- packed f32x2 helpers (2 independent IEEE-rn fp32 lanes) ---
__device__ __forceinline__ ull f2_add(ull a, ull b) {
    ull r; asm("add.rn.f32x2 %0, %1, %2;" : "=l"(r) : "l"(a), "l"(b)); return r;
}

// ---------------------------------------------------------------------------
// spacer: keeps the 4-launch pattern that made ncu's "-s 5 -c 1" capture k2
// ---------------------------------------------------------------------------
__global__ void k_spacer() {
    if (blockIdx.x == 1u << 30) g_spacer_sink = 1;   // never taken
}

// ---------------------------------------------------------------------------
// K0: build WiT and WrT
// ---------------------------------------------------------------------------
__global__ void k0_prep(const float* __restrict__ Wi, const float* __restrict__ Wr) {
    int idx = blockIdx.x * 256 + threadIdx.x;
    if (idx < NIN * HID) {
        int k = idx >> 8;
        int h = idx & 255;
        g_wiT[idx] = Wi[h * NIN + k];
    }
    if (idx < HID * HID) {
        int k = idx >> 8;
        int h = idx & 255;
        g_wrT[idx] = Wr[h * HID + k];
    }
}

// ---------------------------------------------------------------------------
// K1: EXACT R11 kernel (best known: ~390us). XW[r][h] = split-K=8 sum over
// {k : x[r][k]=1} of WiT[k][h]; weight rows via L1 LDG.128, x via __ldcs.
// 800 CTAs x 1024 threads; warp owns 2 rows; lane owns h=lane*4..+3,128+...
// ---------------------------------------------------------------------------
#define K1_THREADS 1024
#define RPW 2                        // rows per warp
#define RPC 64                       // rows per CTA (32 warps * 2)
#define KCHUNK 98
#define NCHUNK 8

__global__ __launch_bounds__(K1_THREADS) void k1_xw(const float* __restrict__ x) {
    const int tid  = threadIdx.x;
    const int lane = tid & 31;
    const int wrp  = tid >> 5;
    const int rbase = blockIdx.x * RPC + wrp * RPW;

    ull tot[RPW][4];                 // running split-K totals
#pragma unroll
    for (int r = 0; r < RPW; ++r)
#pragma unroll
        for (int j = 0; j < 4; ++j) tot[r][j] = 0ULL;

    for (int ch = 0; ch < NCHUNK; ++ch) {
        const float* wch = g_wiT + (size_t)ch * KCHUNK * HID;
#pragma unroll
        for (int r = 0; r < RPW; ++r) {
            const float* xr = x + (size_t)(rbase + r) * NIN + ch * KCHUNK;
            ull p0 = 0, p1 = 0, p2 = 0, p3 = 0;    // chunk partial
#pragma unroll
            for (int w4 = 0; w4 < 4; ++w4) {
                const bool lv = (w4 < 3) || (lane < 2);   // 98 = 3*32 + 2
                float xv = lv ? __ldcs(&xr[w4 * 32 + lane]) : 0.0f;
                unsigned m = __ballot_sync(0xffffffffu, xv != 0.0f);
                while (m) {
                    int kl = w4 * 32 + __ffs(m) - 1;
                    m &= m - 1;
                    const float* wrow = wch + kl * HID;
                    ulonglong2 wa = *(const ulonglong2*)(wrow + lane * 4);
                    ulonglong2 wb = *(const ulonglong2*)(wrow + 128 + lane * 4);
                    p0 = f2_add(p0, wa.x);
                    p1 = f2_add(p1, wa.y);
                    p2 = f2_add(p2, wb.x);
                    p3 = f2_add(p3, wb.y);
                }
            }
            tot[r][0] = f2_add(tot[r][0], p0);   // ascending chunk combine
            tot[r][1] = f2_add(tot[r][1], p1);
            tot[r][2] = f2_add(tot[r][2], p2);
            tot[r][3] = f2_add(tot[r][3], p3);
        }
    }

#pragma unroll
    for (int r = 0; r < RPW; ++r) {
        float* o = g_xw + (size_t)(rbase + r) * HID;
        *(ulonglong2*)&o[lane * 4]       = make_ulonglong2(tot[r][0], tot[r][1]);
        *(ulonglong2*)&o[128 + lane * 4] = make_ulonglong2(tot[r][2], tot[r][3]);
    }
}

// ---------------------------------------------------------------------------
// LIF elementwise update, separately rounded fp32 ops (matches reference HLO)
// ---------------------------------------------------------------------------
__device__ __forceinline__ void lif_lane(float& v, float& i, float xw, float rec,
                                         unsigned& z) {
    float vd = __fadd_rn(v, __fmul_rn(0.05f, __fadd_rn(__fsub_rn(0.0f, v), i)));
    float id = __fmul_rn(i, 0.9f);
    z = vd > 0.5f;
    v = z ? 0.0f : vd;
    i = __fadd_rn(__fadd_rn(id, xw), rec);
}

// ---------------------------------------------------------------------------
// K2 (rebuilt for latency): 2 rows/CTA, 128 threads, 512 CTAs (~14 warps/SM,
// all 148 SMs covered). Thread q=tid%64 owns h[4q..4q+4) of row p=tid/64.
// Recurrent drive = split-K=8 over WrT rows from the PREVIOUS step's spike
// mask: per 32-wide word, bits taken ascending in BATCHES OF 4 — all 4
// LDG.128 issued unconditionally (safe fallback address = word base row),
// then folded in ascending order with SEL-masked addends (h ? w : +0;
// +0 is an exact identity under RN). Order identical to R5/R11; only load
// scheduling changes -> 4-way MLP hides L1/L2 latency, zero branches.
// ---------------------------------------------------------------------------
#define K2_ROWS 2
#define K2_THREADS 128
#define F2_ZERO 0ULL

__global__ __launch_bounds__(K2_THREADS) void k2_steps(const float* __restrict__ Wout,
                                                       const float* __restrict__ bout,
                                                       float* __restrict__ out) {
    __shared__ uint32_t s_hist[T_STEPS][K2_ROWS][8];
    __shared__ uint8_t  s_nib[K2_ROWS][64];
    __shared__ float    s_part[K2_ROWS * NL][3];

    const int tid = threadIdx.x;
    const int q   = tid & 63;
    const int p   = tid >> 6;            // row within CTA (0..1)
    const int b0  = blockIdx.x * K2_ROWS;
    const int row = b0 + p;

    float4 v  = make_float4(0.f, 0.f, 0.f, 0.f);
    float4 cu = v;
    float4 xw_cur =
        *(const float4*)&g_xw[((size_t)(0 * BATCH + row) * HID) + q * 4];

    for (int t = 0; t < T_STEPS; ++t) {
        float4 xw_next;
        if (t + 1 < T_STEPS)
            xw_next = *(const float4*)
                &g_xw[((size_t)((t + 1) * BATCH + row) * HID) + q * 4];

        ull rec0 = 0, rec1 = 0;
        if (t > 0) {
            const uint32_t* mrow = s_hist[t - 1][p];
#pragma unroll
            for (int w8 = 0; w8 < 8; ++w8) {
                uint32_t m = mrow[w8];
                const float* wbase = g_wrT + (size_t)w8 * 32 * HID + q * 4;
                ull pw0 = 0, pw1 = 0;            // word partial
                while (m) {
                    // batch of up to 4 ascending bits; loads all issued,
                    // addends SEL-masked -> branchless, exact.
                    int k0 = __ffs(m) - 1;            m &= m - 1;
                    bool h1 = m != 0;
                    int k1 = h1 ? __ffs(m) - 1 : 0;   m &= m - 1;
                    bool h2 = m != 0;
                    int k2 = h2 ? __ffs(m) - 1 : 0;   m &= m - 1;
                    bool h3 = m != 0;
                    int k3 = h3 ? __ffs(m) - 1 : 0;   m &= m - 1;

                    ulonglong2 w0 = *(const ulonglong2*)(wbase + (size_t)k0 * HID);
                    ulonglong2 w1 = *(const ulonglong2*)(wbase + (size_t)k1 * HID);
                    ulonglong2 w2 = *(const ulonglong2*)(wbase + (size_t)k2 * HID);
                    ulonglong2 w3 = *(const ulonglong2*)(wbase + (size_t)k3 * HID);

                    pw0 = f2_add(pw0, w0.x);
                    pw1 = f2_add(pw1, w0.y);
                    pw0 = f2_add(pw0, h1 ? w1.x : F2_ZERO);
                    pw1 = f2_add(pw1, h1 ? w1.y : F2_ZERO);
                    pw0 = f2_add(pw0, h2 ? w2.x : F2_ZERO);
                    pw1 = f2_add(pw1, h2 ? w2.y : F2_ZERO);
                    pw0 = f2_add(pw0, h3 ? w3.x : F2_ZERO);
                    pw1 = f2_add(pw1, h3 ? w3.y : F2_ZERO);
                }
                rec0 = f2_add(rec0, pw0);        // ascending word combine
                rec1 = f2_add(rec1, pw1);
            }
        }
        float2 ra = *(float2*)&rec0;
        float2 rb = *(float2*)&rec1;

        unsigned zx, zy, zz, zw;
        lif_lane(v.x, cu.x, xw_cur.x, ra.x, zx);
        lif_lane(v.y, cu.y, xw_cur.y, ra.y, zy);
        lif_lane(v.z, cu.z, xw_cur.z, rb.x, zz);
        lif_lane(v.w, cu.w, xw_cur.w, rb.y, zw);
        s_nib[p][q] = (uint8_t)(zx | (zy << 1) | (zz << 2) | (zw << 3));
        xw_cur = xw_next;

        __syncthreads();
        if (tid < 16) {
            int r = tid >> 3, w = tid & 7;
            uint32_t word = 0;
#pragma unroll
            for (int j = 0; j < 8; ++j)
                word |= (uint32_t)s_nib[r][w * 8 + j] << (4 * j);
            s_hist[t][r][w] = word;
        }
        __syncthreads();
    }

    // deferred readout (no feedback; ordering perturbs only ~1e-7 relative)
    if (tid < K2_ROWS * NL * 3) {                 // 60 threads
        int pair = tid / 3, seg = tid - pair * 3;
        int g = pair / NL, l = pair - g * NL;
        int t0 = seg * 17;
        int t1 = (seg == 2) ? T_STEPS : t0 + 17;
        float s = 0.0f;
        for (int t = t0; t < t1; ++t) {
#pragma unroll
            for (int w8 = 0; w8 < 8; ++w8) {
                uint32_t m = s_hist[t][g][w8];
                while (m) {
                    int bpos = __ffs(m) - 1;
                    m &= m - 1;
                    s = __fadd_rn(s, Wout[l * HID + w8 * 32 + bpos]);
                }
            }
        }
        s_part[pair][seg] = s;
    }
    __syncthreads();
    if (tid < K2_ROWS * NL) {                     // 20 threads
        int g = tid / NL, l = tid - (tid / NL) * NL;
        float a = __fadd_rn(__fadd_rn(s_part[tid][0], s_part[tid][1]), s_part[tid][2]);
        float val = __fdiv_rn(__fadd_rn(a, __fmul_rn((float)T_STEPS, bout[l])),
                              (float)T_STEPS);
        out[(b0 + g) * NL + l] = val;
    }
}

// ---------------------------------------------------------------------------
extern "C" void kernel_launch(void* const* d_in, const int* in_sizes, int n_in,
                              void* d_out, int out_size) {
    const float* x    = (const float*)d_in[0];
    const float* Wi   = (const float*)d_in[1];
    const float* Wr   = (const float*)d_in[2];
    const float* Wout = (const float*)d_in[3];
    const float* bout = (const float*)d_in[4];
    float* out = (float*)d_out;

    k_spacer<<<1, 32>>>();

    k0_prep<<<(NIN * HID + 255) / 256, 256>>>(Wi, Wr);

    k1_xw<<<NROWS / RPC, K1_THREADS>>>(x);

    k2_steps<<<BATCH / K2_ROWS, K2_THREADS>>>(Wout, bout, out);
}